// round 17
// baseline (speedup 1.0000x reference)
#include <cuda_runtime.h>

#define Bn 64
#define Tn 512
#define Cn 256
#define NC 8                       // num_clusters: min(8, T) = 8, fixed
#define INFV 1e9f
#define GB 2                       // batches interleaved per CTA
#define A0 144                     // SMEM endgame threshold per batch
#define M0 (Tn - A0)               // compact after this merge (368)
#define NM (Tn - NC)               // 504 merges

typedef unsigned long long ull;

static __device__ float g_XN[(size_t)Bn * Tn * Cn];   // 32 MB normalized x
static __device__ float g_D [(size_t)Bn * Tn * Tn];   // 64 MB distance matrices

// monotone (value, index) packing: u64 compare == lexicographic (val, idx)
__device__ __forceinline__ ull dpack(float v, unsigned c) {
    unsigned u = __float_as_uint(v);
    u ^= ((unsigned)(((int)u) >> 31)) | 0x80000000u;
    return ((ull)u << 32) | c;
}
__device__ __forceinline__ void kmin(ull& k, ull o) { if (o < k) k = o; }
// global key: (val<<18)|(row<<9)|col — lexicographic (val,row,col) = flat argmin
__device__ __forceinline__ ull gk_from(ull rowkey, unsigned r) {
    return ((rowkey >> 32) << 18) | ((ull)r << 9) | ((unsigned)rowkey & 511u);
}

// ---------------------------------------------------------------------------
__global__ void knorm_kernel(const float* __restrict__ x) {
    int row  = blockIdx.x * 8 + (threadIdx.x >> 5);
    int lane = threadIdx.x & 31;
    const float* xr = x + (size_t)row * Cn;
    float s = 0.f;
    #pragma unroll
    for (int c = lane; c < Cn; c += 32) { float v = xr[c]; s = fmaf(v, v, s); }
    #pragma unroll
    for (int o = 16; o; o >>= 1) s += __shfl_xor_sync(0xffffffffu, s, o);
    float denom = sqrtf(s) + 1e-8f;
    float* xo = g_XN + (size_t)row * Cn;
    #pragma unroll
    for (int c = lane; c < Cn; c += 32) xo[c] = xr[c] / denom;
}

// no-op: shifts ncu's -s 5 -c 1 capture slot onto kmerge
__global__ void kdummy_kernel() {}

// ---------------------------------------------------------------------------
// Kernel 2: D = 1 - XN @ XN^T, diag = INF.  Upper-triangle tiles only (10/16);
// off-diagonal tiles mirrored via SMEM-staged transpose (bit-identical values).
// ---------------------------------------------------------------------------
__global__ void __launch_bounds__(256, 2) kgram_kernel() {
    __shared__ float As[16][128];
    __shared__ float Bs[16][128];
    __shared__ float Ts[32][129];
    const int TI[10] = {0,0,0,0,1,1,1,2,2,3};
    const int TJ[10] = {0,1,2,3,1,2,3,2,3,3};
    const int b  = blockIdx.z;
    const int iy = TI[blockIdx.x], jx = TJ[blockIdx.x];
    const int i0 = iy * 128;
    const int j0 = jx * 128;
    const int tid = threadIdx.x;
    const int tx = tid & 15, ty = tid >> 4;
    const float* XA = g_XN + ((size_t)b * Tn + i0) * Cn;
    const float* XB = g_XN + ((size_t)b * Tn + j0) * Cn;
    float acc[8][8] = {};
    for (int k0 = 0; k0 < Cn; k0 += 16) {
        #pragma unroll
        for (int q = 0; q < 2; q++) {
            int f   = tid + q * 256;
            int row = f >> 2;
            int k4  = (f & 3) << 2;
            float4 a4 = *(const float4*)(XA + (size_t)row * Cn + k0 + k4);
            float4 b4 = *(const float4*)(XB + (size_t)row * Cn + k0 + k4);
            As[k4+0][row] = a4.x; As[k4+1][row] = a4.y;
            As[k4+2][row] = a4.z; As[k4+3][row] = a4.w;
            Bs[k4+0][row] = b4.x; Bs[k4+1][row] = b4.y;
            Bs[k4+2][row] = b4.z; Bs[k4+3][row] = b4.w;
        }
        __syncthreads();
        #pragma unroll
        for (int kk = 0; kk < 16; kk++) {
            float a[8], bb[8];
            *(float4*)&a[0]  = *(const float4*)&As[kk][ty * 8];
            *(float4*)&a[4]  = *(const float4*)&As[kk][ty * 8 + 4];
            *(float4*)&bb[0] = *(const float4*)&Bs[kk][tx * 8];
            *(float4*)&bb[4] = *(const float4*)&Bs[kk][tx * 8 + 4];
            #pragma unroll
            for (int r = 0; r < 8; r++)
                #pragma unroll
                for (int c = 0; c < 8; c++)
                    acc[r][c] = fmaf(a[r], bb[c], acc[r][c]);
        }
        __syncthreads();
    }
    #pragma unroll
    for (int r = 0; r < 8; r++)
        #pragma unroll
        for (int c = 0; c < 8; c++) {
            int gi = i0 + ty * 8 + r, gj = j0 + tx * 8 + c;
            acc[r][c] = (gi == gj) ? INFV : (1.0f - acc[r][c]);
        }
    #pragma unroll
    for (int r = 0; r < 8; r++) {
        float* drow = g_D + ((size_t)b * Tn + i0 + ty * 8 + r) * Tn + j0 + tx * 8;
        *(float4*)drow       = *(float4*)&acc[r][0];
        *(float4*)(drow + 4) = *(float4*)&acc[r][4];
    }
    if (iy == jx) return;
    const int orow = tid >> 1;
    const int h    = tid & 1;
    #pragma unroll
    for (int q = 0; q < 4; q++) {
        if ((ty >> 2) == q) {
            #pragma unroll
            for (int r = 0; r < 8; r++)
                #pragma unroll
                for (int c = 0; c < 8; c++)
                    Ts[(ty & 3) * 8 + r][tx * 8 + c] = acc[r][c];
        }
        __syncthreads();
        float tmp[16];
        #pragma unroll
        for (int k = 0; k < 16; k++) tmp[k] = Ts[h * 16 + k][orow];
        float* dst = g_D + ((size_t)b * Tn + j0 + orow) * Tn + i0 + q * 32 + h * 16;
        *(float4*)(dst + 0)  = *(float4*)&tmp[0];
        *(float4*)(dst + 4)  = *(float4*)&tmp[4];
        *(float4*)(dst + 8)  = *(float4*)&tmp[8];
        *(float4*)(dst + 12) = *(float4*)&tmp[12];
        __syncthreads();
    }
}

// ---------------------------------------------------------------------------
// Kernel 3: TWO interleaved batch chains per CTA (latency hiding). Per batch:
// exact R9 merge logic (2 phases). Phase B of both batches issues before one
// barrier; phase C of both before the next — independent chains' memory
// latencies overlap. SMEM endgame per batch at alive=A0.
// ---------------------------------------------------------------------------
__global__ void __launch_bounds__(512) kmerge_kernel(float* __restrict__ out) {
    extern __shared__ float dsm[];           // GB * A0*A0 compacted D (endgame)
    const int t = threadIdx.x;
    const int lane = t & 31, warp = t >> 5;
    const int b0 = blockIdx.x * GB;

    __shared__ ull      minkey[GB][Tn];
    __shared__ float    sizes[GB][Tn];
    __shared__ int      assign[GB][Tn], rep[GB][Tn];
    __shared__ int      o2n[Tn];             // compaction scratch (per-g serial)
    __shared__ int      rlist[GB][Tn];       // invalidation list / n2o / scan
    __shared__ unsigned alivem[GB][Tn / 32];
    __shared__ int      cnt2[GB][2];
    __shared__ ull      gkey2[GB][2];

    float* Dg[GB];
    #pragma unroll
    for (int g = 0; g < GB; g++) {
        Dg[g] = g_D + (size_t)(b0 + g) * Tn * Tn;
        sizes[g][t] = 1.f; assign[g][t] = t; rep[g][t] = t; minkey[g][t] = ~0ull;
        if (t < Tn / 32) alivem[g][t] = 0xffffffffu;
        if (t == 0) { cnt2[g][0] = cnt2[g][1] = 0; gkey2[g][0] = gkey2[g][1] = ~0ull; }
    }
    __syncthreads();

    // initial per-row scans, both batches (diag already INF)
    #pragma unroll
    for (int g = 0; g < GB; g++)
        for (int r = warp; r < Tn; r += 16) {
            const float4* rowv = (const float4*)(Dg[g] + (size_t)r * Tn);
            ull k = ~0ull;
            for (int c4 = lane; c4 < Tn / 4; c4 += 32) {
                float4 v = rowv[c4]; unsigned c = c4 * 4;
                kmin(k, dpack(v.x, c));     kmin(k, dpack(v.y, c + 1));
                kmin(k, dpack(v.z, c + 2)); kmin(k, dpack(v.w, c + 3));
            }
            atomicMin(&minkey[g][r], k);
        }
    __syncthreads();
    if (warp == 0) {
        #pragma unroll
        for (int g = 0; g < GB; g++) {
            ull gk = ~0ull;
            #pragma unroll
            for (int q = 0; q < 16; q++) { int r = q * 32 + lane; kmin(gk, gk_from(minkey[g][r], r)); }
            atomicMin(&gkey2[g][1], gk);
        }
    }
    __syncthreads();

    float* Dp[GB]; Dp[0] = Dg[0]; Dp[1] = Dg[1];
    int st = Tn;

    int iv[GB], jv[GB]; float niv[GB], njv[GB];

    for (int m = 1; m <= NM; ++m) {
        const int p = m & 1;

        // ======== phase B (both batches): finalize + merged-row build ========
        #pragma unroll
        for (int g = 0; g < GB; g++) {
            ull gg = gkey2[g][p];
            int gc = (int)(gg & 511u), gr = (int)((gg >> 9) & 511u);
            int i  = min(gr, gc), j = max(gr, gc);
            iv[g] = i; jv[g] = j;
            float ni = sizes[g][i], nj = sizes[g][j];
            niv[g] = ni; njv[g] = nj;
            bool isalive = (alivem[g][t >> 5] >> (t & 31)) & 1u;

            if (t == j) {
                minkey[g][j] = ~0ull;
                atomicAnd(&alivem[g][j >> 5], ~(1u << (j & 31)));
            } else if (t == i) {
                minkey[g][i] = ~0ull;              // row i always rescanned
                Dp[g][(size_t)i * st + i] = INFV;
            } else if (isalive) {
                float a  = Dp[g][(size_t)i * st + t];
                float dj = Dp[g][(size_t)j * st + t];
                float nr = __fdiv_rn(__fadd_rn(__fmul_rn(ni, a), __fmul_rn(nj, dj)),
                                     __fadd_rn(ni, nj));
                Dp[g][(size_t)i * st + t] = nr;    // row i
                Dp[g][(size_t)t * st + i] = nr;    // col i (matrix stays current)
                ull key = minkey[g][t];
                int mc  = (int)((unsigned)key);
                if (mc == i || mc == j) {
                    rlist[g][atomicAdd(&cnt2[g][p], 1)] = t;
                    minkey[g][t] = ~0ull;          // owner resets before rescan
                } else {
                    ull cand = dpack(nr, (unsigned)i);
                    if (cand < key) minkey[g][t] = cand;
                }
            }
            if (t == 509) cnt2[g][p ^ 1] = 0;      // for merge m+1
            if (t == 510) gkey2[g][p ^ 1] = ~0ull; // for merge m+1
            if (assign[g][t] == rep[g][j]) assign[g][t] = rep[g][i];
        }
        __syncthreads();

        // ======== phase C (both batches): rescans + next global argmin =======
        #pragma unroll
        for (int g = 0; g < GB; g++) {
            const int i = iv[g];
            if (t == 511) { sizes[g][i] = niv[g] + njv[g]; sizes[g][jv[g]] = 0.f; }
            if (warp == 0) {
                ull gk = ~0ull;
                const int nq = (st == Tn) ? 16 : (A0 + 31) / 32;
                for (int q = 0; q < nq; q++) { int r = q * 32 + lane; kmin(gk, gk_from(minkey[g][r], r)); }
                atomicMin(&gkey2[g][p ^ 1], gk);
            } else {
                const int c_ = cnt2[g][p];
                for (int li = warp - 1; li < c_ + 1; li += 15) {
                    int rr = (li == 0) ? i : rlist[g][li - 1];
                    const float* rowp = Dp[g] + (size_t)rr * st;
                    ull k = ~0ull;
                    for (int c4 = lane; c4 < st / 4; c4 += 32) {
                        unsigned mb = (alivem[g][c4 >> 3] >> ((c4 & 7) * 4)) & 0xFu;
                        if (!mb) continue;
                        float4 v = *(const float4*)(rowp + c4 * 4);
                        unsigned c = c4 * 4;
                        if (mb & 1u) kmin(k, dpack(v.x, c));
                        if (mb & 2u) kmin(k, dpack(v.y, c + 1));
                        if (mb & 4u) kmin(k, dpack(v.z, c + 2));
                        if (mb & 8u) kmin(k, dpack(v.w, c + 3));
                    }
                    atomicMin(&minkey[g][rr], k);
                    atomicMin(&gkey2[g][p ^ 1], gk_from(k, (unsigned)rr));
                }
            }
        }

        // ====== one-time compaction into SMEM at alive == A0 (per batch) ======
        if (m == M0) {
            for (int g = 0; g < GB; g++) {
                __syncthreads();
                int alv = (alivem[g][t >> 5] >> (t & 31)) & 1;
                o2n[t] = alv;
                __syncthreads();
                for (int off = 1; off < Tn; off <<= 1) {
                    int add = (t >= off) ? o2n[t - off] : 0;
                    __syncthreads();
                    o2n[t] += add;
                    __syncthreads();
                }
                if (alv) rlist[g][o2n[t] - 1] = t;          // n2o map
                __syncthreads();
                ull nk = ~0ull; float ns = 0.f; int nrp = 0;
                if (t < A0) {
                    int o = rlist[g][t];
                    ull ok = minkey[g][o];
                    unsigned oc = (unsigned)ok;              // old col (alive)
                    nk = (ok & 0xFFFFFFFF00000000ull) | (unsigned)(o2n[oc] - 1);
                    ns = sizes[g][o]; nrp = rep[g][o];
                }
                float* dg = dsm + (size_t)g * A0 * A0;
                for (int idx = t; idx < A0 * A0; idx += Tn) {
                    int rn = idx / A0, cn = idx - rn * A0;
                    dg[idx] = Dg[g][(size_t)rlist[g][rn] * Tn + rlist[g][cn]];
                }
                __syncthreads();
                minkey[g][t] = (t < A0) ? nk : ~0ull;
                if (t < A0) { sizes[g][t] = ns; rep[g][t] = nrp; }
                if (t < Tn / 32)
                    alivem[g][t] = (t < A0 / 32) ? 0xffffffffu
                              : (t == A0 / 32 ? ((1u << (A0 & 31)) - 1u) : 0u);
                if (t == 0) {
                    ull gg = gkey2[g][p ^ 1];
                    unsigned ggc = gg & 511u, ggr = (gg >> 9) & 511u;
                    gkey2[g][p ^ 1] = ((gg >> 18) << 18)
                                 | ((ull)(unsigned)(o2n[ggr] - 1) << 9)
                                 | (unsigned)(o2n[ggc] - 1);
                    cnt2[g][0] = cnt2[g][1] = 0;
                }
            }
            __syncthreads();
            Dp[0] = dsm; Dp[1] = dsm + (size_t)A0 * A0;
            st = A0;
        }
        __syncthreads();
    }

    // ---- canonical relabel (both batches, fused scans) ----
    #pragma unroll
    for (int g = 0; g < GB; g++) rlist[g][t] = (assign[g][t] == t) ? 1 : 0;
    __syncthreads();
    for (int off = 1; off < Tn; off <<= 1) {
        int v[GB];
        #pragma unroll
        for (int g = 0; g < GB; g++) v[g] = (t >= off) ? rlist[g][t - off] : 0;
        __syncthreads();
        #pragma unroll
        for (int g = 0; g < GB; g++) rlist[g][t] += v[g];
        __syncthreads();
    }
    #pragma unroll
    for (int g = 0; g < GB; g++)
        out[(size_t)(b0 + g) * Tn + t] = (float)(rlist[g][assign[g][t]] - 1);
}

// ---------------------------------------------------------------------------
extern "C" void kernel_launch(void* const* d_in, const int* in_sizes, int n_in,
                              void* d_out, int out_size) {
    const float* x = (const float*)d_in[0];
    for (int k = 0; k < n_in; k++)
        if (in_sizes[k] >= Bn * Tn * Cn) { x = (const float*)d_in[k]; break; }
    float* out = (float*)d_out;

    knorm_kernel<<<(Bn * Tn) / 8, 256>>>(x);
    dim3 gg(10, 1, Bn);                         // upper-triangle tiles only
    kgram_kernel<<<gg, 256>>>();
    kdummy_kernel<<<1, 32>>>();                 // ncu capture-slot steering
    const int dsm_bytes = GB * A0 * A0 * (int)sizeof(float);
    cudaFuncSetAttribute(kmerge_kernel,
                         cudaFuncAttributeMaxDynamicSharedMemorySize, dsm_bytes);
    kmerge_kernel<<<Bn / GB, Tn, dsm_bytes>>>(out);
}